// round 17
// baseline (speedup 1.0000x reference)
#include <cuda_runtime.h>
#include <cuda_bf16.h>
#include <cuda_fp16.h>
#include <math.h>
#include <cstdint>

#define H     300
#define G     900
#define NB    1024
#define LSEQ  64
#define NTHREADS 320
#define NNODES 49152

// ---- input GEMM config (fp16 2.5-term) ----
#define K320  320
#define NKB3  10                   // k-blocks of 32
#define NP    1024
#define MT    128
#define G2STG 32768                // stage: Ahi|Alo|Bhi|Blo, each 128x64B
#define G2TOT (3 * G2STG)          // 98304

// ---- recurrent mma config (fp16 2.5-term, R16-proven) ----
#define GP    304
#define RROWS 912
#define RPR   19
#define WSTG  (RROWS * 32)         // 29184
#define HSS   648
#define RBT   16
#define RNT   608
#define NCW   19
#define HSBUF (RBT * HSS * 2)
#define CSCL  2048.0f
#define CINV  4.8828125e-4f

// recur smem (6-stage ring)
#define SM_W    0
#define SM_HS   (6 * WSTG)                    // 175104
#define SM_BH   (SM_HS + 2 * HSBUF)           // 216576
#define SM_BI   (SM_BH + 3600)                // 220176
#define SM_MISC (SM_BI + 3600)                // 223776
#define SM_TOT  (SM_MISC + 128)               // 223904

__device__ __forceinline__ float sigm(float x) { return 1.f / (1.f + __expf(-x)); }
__device__ __forceinline__ float tanh_fast(float x) {
    float s = 1.f / (1.f + __expf(-2.f * x));
    return 2.f * s - 1.f;
}
__device__ __forceinline__ uint32_t smem_u32(const void* p) {
    uint32_t a;
    asm("{ .reg .u64 t; cvta.to.shared.u64 t, %1; cvt.u32.u64 %0, t; }" : "=r"(a) : "l"(p));
    return a;
}
__device__ __forceinline__ float ldcs(const float* p) {
    float v; asm volatile("ld.global.cs.f32 %0, [%1];" : "=f"(v) : "l"(p)); return v;
}
__device__ __forceinline__ void stcs(float* p, float v) {
    asm volatile("st.global.cs.f32 [%0], %1;" :: "l"(p), "f"(v));
}
__device__ __forceinline__ float h16f(uint32_t reg, int hi) {
    unsigned short us = hi ? (unsigned short)(reg >> 16) : (unsigned short)(reg & 0xffff);
    __half h; *(unsigned short*)&h = us;
    return __half2float(h);
}

#define MMA_F32H(ac, Af, B0, B1)                                                    \
    asm volatile("mma.sync.aligned.m16n8k16.row.col.f32.f16.f16.f32 "               \
        "{%0,%1,%2,%3}, {%4,%5,%6,%7}, {%8,%9}, {%0,%1,%2,%3};"                     \
        : "+f"((ac)[0]), "+f"((ac)[1]), "+f"((ac)[2]), "+f"((ac)[3])                \
        : "r"((Af)[0]), "r"((Af)[1]), "r"((Af)[2]), "r"((Af)[3]), "r"(B0), "r"(B1))
#define MMA_F16H(cc, Af, B0, B1)                                                    \
    asm volatile("mma.sync.aligned.m16n8k16.row.col.f16.f16.f16.f16 "               \
        "{%0,%1}, {%2,%3,%4,%5}, {%6,%7}, {%0,%1};"                                 \
        : "+r"((cc)[0]), "+r"((cc)[1])                                              \
        : "r"((Af)[0]), "r"((Af)[1]), "r"((Af)[2]), "r"((Af)[3]), "r"(B0), "r"(B1))

// ---------------- device scratch ----------------
__device__ __align__(16) __half g_abf2[2][(size_t)NNODES * K320];   // [part][node][k]
__device__ __align__(16) __half g_bbf2[2][2][(size_t)NP * K320];    // [dir][part][g][k]
__device__ __align__(16) __half g_gwr[(size_t)2 * RPR * 2 * RROWS * 16];
__device__ float g_xg[2][(size_t)NNODES * G];
__device__ float g_h0[NB * H];
__device__ int   g_sstart[NB];
__device__ int   g_slen[NB];

// ---------------- 1) merged prep: seg | convA | convB | convW ----------------
__global__ void __launch_bounds__(256) k_prep(const float* __restrict__ node,
                                              const float* __restrict__ bias,
                                              const int* __restrict__ batch,
                                              const int* __restrict__ pos,
                                              const float* __restrict__ wif,
                                              const float* __restrict__ wib,
                                              const float* __restrict__ whf,
                                              const float* __restrict__ whb,
                                              int n) {
    __shared__ float sb[H];
    const int bx = blockIdx.x, tid = threadIdx.x;
    if (bx < 64) {
        for (int i = bx * 256 + tid; i < n; i += 64 * 256) {
            int b = batch[i];
            if (pos[i] == 0) g_sstart[b] = i;
            if (i == n - 1 || batch[i + 1] != b) g_slen[b] = pos[i] + 1;
        }
    } else if (bx < 64 + n) {
        int i = bx - 64;
        for (int k = tid; k < H; k += 256) {
            float v = node[(size_t)i * H + k] + bias[k];
            sb[k] = v > 0.f ? v : 0.f;
        }
        __syncthreads();
        __half* d0 = g_abf2[0] + (size_t)i * K320;
        __half* d1 = g_abf2[1] + (size_t)i * K320;
        for (int kp = tid; kp < K320; kp += 256) {
            __half hi = __float2half(0.f), lo = __float2half(0.f);
            if (kp < H) {
                float m = sb[kp];
                hi = __float2half(m);
                lo = __float2half((m - __half2float(hi)) * CSCL);
            }
            d0[kp] = hi; d1[kp] = lo;
        }
    } else if (bx < 64 + n + 512) {
        const int tot = 2 * 2 * NP * K320;
        int bb = bx - 64 - n;
        for (int idx = bb * 256 + tid; idx < tot; idx += 512 * 256) {
            int kp = idx % K320;
            int r1 = idx / K320;
            int g = r1 % NP;
            int r2 = r1 / NP;
            int part = r2 & 1;
            int dir = r2 >> 1;
            __half o = __float2half(0.f);
            if (g < G && kp < H) {
                const float* w = dir ? wib : wif;
                float v = w[(size_t)g * H + kp];
                __half hi = __float2half(v);
                o = part ? __float2half((v - __half2float(hi)) * CSCL) : hi;
            }
            g_bbf2[dir][part][(size_t)g * K320 + kp] = o;
        }
    } else {
        const int tot = 2 * RPR * 2 * RROWS * 16;
        int bb = bx - 64 - n - 512;
        for (int idx = bb * 256 + tid; idx < tot; idx += 256 * 256) {
            int c = idx & 15;
            int r1 = idx >> 4;
            int row = r1 % RROWS;
            int r2 = r1 / RROWS;
            int part = r2 & 1;
            int r3 = r2 >> 1;
            int pr = r3 % RPR;
            int dir = r3 / RPR;
            int gate = row / GP, j = row % GP;
            int k = pr * 16 + c;
            __half o = __float2half(0.f);
            if (j < H && k < H) {
                const float* w = dir ? whb : whf;
                float v = w[(size_t)(gate * H + j) * H + k];
                __half hi = __float2half(v);
                o = part ? __float2half((v - __half2float(hi)) * CSCL) : hi;
            }
            g_gwr[idx] = o;
        }
    }
}

// ---------------- 2) h0 = per-graph segment max ----------------
__global__ void __launch_bounds__(NTHREADS) k_h0(const float* __restrict__ node) {
    int b = blockIdx.x, h = threadIdx.x;
    if (h >= H) return;
    int s = g_sstart[b], l = g_slen[b];
    float m = -3.402823466e38f;
    for (int i = 0; i < l; ++i) m = fmaxf(m, node[(size_t)(s + i) * H + h]);
    g_h0[b * H + h] = m;
}

// ---------------- 3) input GEMM: fp16 2.5-term ----------------
__global__ void __launch_bounds__(512, 1) k_gemm2(const float* __restrict__ bih_f,
                                                  const float* __restrict__ bih_b) {
    extern __shared__ unsigned char gsm[];
    const int tid = threadIdx.x, lane = tid & 31, wid = tid >> 5;
    const int dir = blockIdx.x >> 3, ntile = blockIdx.x & 7;
    const int m0 = blockIdx.y * MT, n0 = ntile * 128;
    const int wm = wid & 3, wn = wid >> 2;

    const __half* __restrict__ Ah = g_abf2[0] + (size_t)m0 * K320;
    const __half* __restrict__ Al = g_abf2[1] + (size_t)m0 * K320;
    const __half* __restrict__ Bh = g_bbf2[dir][0] + (size_t)n0 * K320;
    const __half* __restrict__ Bl = g_bbf2[dir][1] + (size_t)n0 * K320;
    const uint32_t s0 = smem_u32(gsm);

    float d[2][4][4];
    uint32_t cf[2][4][2];
#pragma unroll
    for (int mi = 0; mi < 2; ++mi)
#pragma unroll
        for (int ni = 0; ni < 4; ++ni) {
#pragma unroll
            for (int e = 0; e < 4; ++e) d[mi][ni][e] = 0.f;
            cf[mi][ni][0] = 0u; cf[mi][ni][1] = 0u;
        }

#define ISSUE_STG2(kb, stg) do {                                                    \
    _Pragma("unroll")                                                               \
    for (int _i = 0; _i < 4; ++_i) {                                                \
        int _c = _i * 512 + tid;                                                    \
        int _part = _c >> 9, _r = (_c >> 2) & 127, _q = _c & 3;                     \
        const __half* _sp = (_part == 0) ? Ah : (_part == 1) ? Al                   \
                          : (_part == 2) ? Bh : Bl;                                 \
        const void* _src = _sp + (size_t)_r * K320 + (kb) * 32 + _q * 8;            \
        uint32_t _dst = s0 + (stg) * G2STG + _part * 8192 + _r * 64 + _q * 16;      \
        asm volatile("cp.async.cg.shared.global [%0], [%1], 16;" :: "r"(_dst), "l"(_src)); \
    }                                                                               \
    asm volatile("cp.async.commit_group;" ::: "memory");                            \
} while (0)

    ISSUE_STG2(0, 0);
    ISSUE_STG2(1, 1);
    const bool tail = (ntile == 7);
    const int nimax = tail ? ((wn == 0) ? 1 : 0) : 4;
    int stg = 0;
    for (int kb = 0; kb < NKB3; ++kb) {
        if (kb <= NKB3 - 2) { asm volatile("cp.async.wait_group 1;" ::: "memory"); }
        else                { asm volatile("cp.async.wait_group 0;" ::: "memory"); }
        __syncthreads();
        const uint32_t* sbp = (const uint32_t*)(gsm + stg * G2STG);
#pragma unroll
        for (int ks = 0; ks < 2; ++ks) {
            uint32_t ahi[2][4], alo[2][4];
#pragma unroll
            for (int mi = 0; mi < 2; ++mi) {
                int r0 = wm * 32 + mi * 16 + (lane >> 2);
                int w0 = r0 * 16 + ks * 8 + (lane & 3);
                int w8 = (r0 + 8) * 16 + ks * 8 + (lane & 3);
                ahi[mi][0] = sbp[w0];        ahi[mi][1] = sbp[w8];
                ahi[mi][2] = sbp[w0 + 4];    ahi[mi][3] = sbp[w8 + 4];
                alo[mi][0] = sbp[2048 + w0]; alo[mi][1] = sbp[2048 + w8];
                alo[mi][2] = sbp[2048 + w0 + 4]; alo[mi][3] = sbp[2048 + w8 + 4];
            }
            for (int ni = 0; ni < nimax; ++ni) {
                int cn = wn * 32 + ni * 8 + (lane >> 2);
                int wq = cn * 16 + ks * 8 + (lane & 3);
                uint32_t bh0 = sbp[4096 + wq], bh1 = sbp[4096 + wq + 4];
                uint32_t bl0 = sbp[6144 + wq], bl1 = sbp[6144 + wq + 4];
#pragma unroll
                for (int mi = 0; mi < 2; ++mi) {
                    MMA_F32H(d[mi][ni], ahi[mi], bh0, bh1);
                    MMA_F16H(cf[mi][ni], ahi[mi], bl0, bl1);
                    MMA_F16H(cf[mi][ni], alo[mi], bh0, bh1);
                }
            }
        }
        if (kb + 2 < NKB3) {
            int ns = stg + 2; if (ns >= 3) ns -= 3;
            ISSUE_STG2(kb + 2, ns);
        }
        if (++stg == 3) stg = 0;
    }
#undef ISSUE_STG2

    const float* __restrict__ bih = dir ? bih_b : bih_f;
    float* __restrict__ xg = g_xg[dir];
#pragma unroll
    for (int mi = 0; mi < 2; ++mi) {
        int r0 = m0 + wm * 32 + mi * 16 + (lane >> 2);
        for (int ni = 0; ni < nimax; ++ni) {
            int g = n0 + wn * 32 + ni * 8 + (lane & 3) * 2;
            if (g < G) {
                float bg0 = bih[g], bg1 = bih[g + 1];
                float c00 = h16f(cf[mi][ni][0], 0) * CINV;
                float c01 = h16f(cf[mi][ni][0], 1) * CINV;
                float c10 = h16f(cf[mi][ni][1], 0) * CINV;
                float c11 = h16f(cf[mi][ni][1], 1) * CINV;
                *(float2*)(xg + (size_t)r0 * G + g) =
                    make_float2(d[mi][ni][0] + c00 + bg0, d[mi][ni][1] + c01 + bg1);
                *(float2*)(xg + (size_t)(r0 + 8) * G + g) =
                    make_float2(d[mi][ni][2] + c10 + bg0, d[mi][ni][3] + c11 + bg1);
            }
        }
    }
}

// ---------------- 4) recurrent GRU: fp16 2.5-term, 6-stage ring ----------------
__global__ void __launch_bounds__(RNT, 1) k_recur_mma(const float* __restrict__ bih_f,
                                                      const float* __restrict__ bih_b,
                                                      const float* __restrict__ bhh_f,
                                                      const float* __restrict__ bhh_b,
                                                      float* __restrict__ out) {
    extern __shared__ char smem[];
    float* sbhh = (float*)(smem + SM_BH);
    float* sbih = (float*)(smem + SM_BI);
    int*   sst  = (int*)(smem + SM_MISC);
    int*   sln  = sst + RBT;

    const int tid = threadIdx.x, lane = tid & 31, wid = tid >> 5;
    const int dir = blockIdx.y;
    const int b0 = blockIdx.x * RBT;
    const uint32_t swb = smem_u32(smem);

    uint32_t afro[3];
    {
        int lsel = lane >> 3, lrow = lane & 7;
        int half = lsel >> 1;
#pragma unroll
        for (int i = 0; i < 3; ++i) {
            int row = (wid + NCW * i) * 16 + lrow + ((lsel & 1) << 3);
            afro[i] = row * 32 + ((half ^ ((row >> 2) & 1)) << 4);
        }
    }

    const __half* __restrict__ gw = g_gwr + (size_t)dir * RPR * 2 * RROWS * 16;
    const float* __restrict__ xg = g_xg[dir];

#define ISSUE_PAIR(pfc, sA, sB) do {                                                \
    const char* _s0 = (const char*)(gw + ((size_t)(pfc) * 2)     * (RROWS * 16));   \
    const char* _s1 = (const char*)(gw + ((size_t)(pfc) * 2 + 1) * (RROWS * 16));   \
    _Pragma("unroll")                                                               \
    for (int _i = 0; _i < 3; ++_i) {                                                \
        int _row = (wid + NCW * _i) * 16 + (lane >> 1);                             \
        int _half = lane & 1;                                                       \
        int _hsw = _half ^ ((_row >> 2) & 1);                                       \
        uint32_t _off = _row * 32 + (_hsw << 4);                                    \
        uint32_t _go  = _row * 32 + _half * 16;                                     \
        asm volatile("cp.async.cg.shared.global [%0], [%1], 16;"                    \
                     :: "r"(swb + (sA) * WSTG + _off), "l"(_s0 + _go));             \
        asm volatile("cp.async.cg.shared.global [%0], [%1], 16;"                    \
                     :: "r"(swb + (sB) * WSTG + _off), "l"(_s1 + _go));             \
    }                                                                               \
    asm volatile("cp.async.commit_group;" ::: "memory");                            \
} while (0)

#define LDM_A(dst, stg) do {                                                        \
    uint32_t _wb = swb + (uint32_t)(stg) * WSTG;                                    \
    _Pragma("unroll")                                                               \
    for (int _i = 0; _i < 3; ++_i) {                                                \
        asm volatile("ldmatrix.sync.aligned.m8n8.x4.shared.b16 "                    \
                     "{%0,%1,%2,%3}, [%4];"                                         \
                     : "=r"((dst)[_i][0]), "=r"((dst)[_i][1]),                      \
                       "=r"((dst)[_i][2]), "=r"((dst)[_i][3])                       \
                     : "r"(_wb + afro[_i]));                                        \
    }                                                                               \
} while (0)

    ISSUE_PAIR(0, 0, 1);
    ISSUE_PAIR(1, 2, 3);
    ISSUE_PAIR(2, 4, 5);

    // ---- init ----
    if (tid < RBT) { sst[tid] = g_sstart[b0 + tid]; sln[tid] = g_slen[b0 + tid]; }
    {
        uint32_t* hz = (uint32_t*)(smem + SM_HS);
        for (int i = tid; i < 2 * RBT * (HSS / 2); i += RNT) hz[i] = 0u;
        const float* bhh = dir ? bhh_b : bhh_f;
        const float* bih = dir ? bih_b : bih_f;
        for (int i = tid; i < G; i += RNT) { sbhh[i] = bhh[i]; sbih[i] = bih[i]; }
    }
    __syncthreads();
    {
        __half* hs0 = (__half*)(smem + SM_HS);
        for (int it = tid; it < RBT * H; it += RNT) {
            int j = it >> 4, b = it & 15;
            float v = g_h0[(b0 + b) * H + j];
            __half hh = __float2half(v);
            hs0[b * HSS + j] = hh;
            hs0[b * HSS + 320 + j] = __float2half((v - __half2float(hh)) * CSCL);
        }
    }
    const int j0 = wid * 16 + (lane >> 2);
    float hp[2][4];
#pragma unroll
    for (int nt = 0; nt < 2; ++nt)
#pragma unroll
        for (int e = 0; e < 4; ++e) {
            int j = j0 + ((e >> 1) << 3);
            int b = nt * 8 + (lane & 3) * 2 + (e & 1);
            hp[nt][e] = (j < H) ? g_h0[(b0 + b) * H + j] : 0.f;
        }
    __syncthreads();

    int slot3 = 0;                       // ring pair-slot, carried across steps
    for (int s = 0; s < LSEQ; ++s) {
        int t = dir ? (LSEQ - 1 - s) : s;
        const int cur = s & 1, nxt = cur ^ 1;
        const uint32_t* hs32 = (const uint32_t*)(smem + SM_HS + cur * HSBUF);

        float acc[3][2][4];
        uint32_t cf[3][2][2];
#pragma unroll
        for (int g = 0; g < 3; ++g)
#pragma unroll
            for (int nt = 0; nt < 2; ++nt) {
#pragma unroll
                for (int e = 0; e < 4; ++e) acc[g][nt][e] = 0.f;
                cf[g][nt][0] = 0u; cf[g][nt][1] = 0u;
            }

#pragma unroll 1
        for (int kc = 0; kc < RPR; ++kc) {
            const int sA = 2 * slot3, sB = sA + 1;
            asm volatile("cp.async.wait_group 2;" ::: "memory");   // pair kc landed
            const int hk = kc * 8;
            uint32_t Ahi[3][4];
            LDM_A(Ahi, sA);
            uint32_t bh[2][2];
#pragma unroll
            for (int nt = 0; nt < 2; ++nt) {
                int rb = (nt * 8 + (lane >> 2)) * (HSS / 2);
                bh[nt][0] = hs32[rb + hk + (lane & 3)];
                bh[nt][1] = hs32[rb + hk + 4 + (lane & 3)];
            }
#pragma unroll
            for (int i = 0; i < 3; ++i)
#pragma unroll
                for (int nt = 0; nt < 2; ++nt)
                    MMA_F32H(acc[i][nt], Ahi[i], bh[nt][0], bh[nt][1]);
            uint32_t bl[2][2];
#pragma unroll
            for (int nt = 0; nt < 2; ++nt) {
                int rb = (nt * 8 + (lane >> 2)) * (HSS / 2);
                bl[nt][0] = hs32[rb + 160 + hk + (lane & 3)];
                bl[nt][1] = hs32[rb + 160 + hk + 4 + (lane & 3)];
            }
#pragma unroll
            for (int i = 0; i < 3; ++i)
#pragma unroll
                for (int nt = 0; nt < 2; ++nt)
                    MMA_F16H(cf[i][nt], Ahi[i], bl[nt][0], bl[nt][1]);
            uint32_t Alo[3][4];
            LDM_A(Alo, sB);
            int pfc = kc + 3; if (pfc >= RPR) pfc -= RPR;
            ISSUE_PAIR(pfc, sA, sB);
#pragma unroll
            for (int i = 0; i < 3; ++i)
#pragma unroll
                for (int nt = 0; nt < 2; ++nt)
                    MMA_F16H(cf[i][nt], Alo[i], bh[nt][0], bh[nt][1]);
            slot3 = (slot3 + 1 == 3) ? 0 : slot3 + 1;
        }

        // ---- pointwise in registers; new h-split to buffer nxt ----
        __half* hsbn = (__half*)(smem + SM_HS + nxt * HSBUF);
#pragma unroll
        for (int nt = 0; nt < 2; ++nt)
#pragma unroll
            for (int e = 0; e < 4; ++e) {
                int j = j0 + ((e >> 1) << 3);
                int b = nt * 8 + (lane & 3) * 2 + (e & 1);
                if (j < H) {
                    bool valid = t < sln[b];
                    float x0, x1, x2;
                    if (valid) {
                        const float* xr = xg + (size_t)(sst[b] + t) * G;
                        x0 = ldcs(xr + j); x1 = ldcs(xr + H + j); x2 = ldcs(xr + 2 * H + j);
                    } else {
                        x0 = sbih[j]; x1 = sbih[H + j]; x2 = sbih[2 * H + j];
                    }
                    float c0 = h16f(cf[0][nt][e >> 1], e & 1) * CINV;
                    float c1 = h16f(cf[1][nt][e >> 1], e & 1) * CINV;
                    float c2 = h16f(cf[2][nt][e >> 1], e & 1) * CINV;
                    float r  = sigm(x0 + acc[0][nt][e] + c0 + sbhh[j]);
                    float z  = sigm(x1 + acc[1][nt][e] + c1 + sbhh[H + j]);
                    float nn = tanh_fast(x2 + r * (acc[2][nt][e] + c2 + sbhh[2 * H + j]));
                    float hv = (1.f - z) * nn + z * hp[nt][e];
                    hp[nt][e] = hv;
                    __half hh = __float2half(hv);
                    hsbn[b * HSS + j] = hh;
                    hsbn[b * HSS + 320 + j] = __float2half((hv - __half2float(hh)) * CSCL);
                    if (valid)
                        stcs(out + (size_t)(sst[b] + t) * (2 * H) + dir * H + j, hv);
                }
            }
        __syncthreads();
    }
    asm volatile("cp.async.wait_group 0;" ::: "memory");
#undef ISSUE_PAIR
#undef LDM_A
}

// ---------------- host entry ----------------
extern "C" void kernel_launch(void* const* d_in, const int* in_sizes, int n_in,
                              void* d_out, int out_size) {
    const float* node   = (const float*)d_in[0];
    const int*   batch  = (const int*)d_in[1];
    const int*   pos    = (const int*)d_in[2];
    const float* bias   = (const float*)d_in[3];
    const float* w_ih_f = (const float*)d_in[4];
    const float* w_hh_f = (const float*)d_in[5];
    const float* b_ih_f = (const float*)d_in[6];
    const float* b_hh_f = (const float*)d_in[7];
    const float* w_ih_b = (const float*)d_in[8];
    const float* w_hh_b = (const float*)d_in[9];
    const float* b_ih_b = (const float*)d_in[10];
    const float* b_hh_b = (const float*)d_in[11];
    float* out = (float*)d_out;
    int n = in_sizes[0] / H;

    cudaFuncSetAttribute(k_gemm2, cudaFuncAttributeMaxDynamicSharedMemorySize, G2TOT);
    cudaFuncSetAttribute(k_recur_mma, cudaFuncAttributeMaxDynamicSharedMemorySize, SM_TOT);

    int gprep = 64 + n + 512 + 256;
    k_prep<<<gprep, 256>>>(node, bias, batch, pos, w_ih_f, w_ih_b, w_hh_f, w_hh_b, n);
    k_h0<<<NB, NTHREADS>>>(node);
    k_gemm2<<<dim3(16, n / MT), 512, G2TOT>>>(b_ih_f, b_ih_b);
    k_recur_mma<<<dim3(NB / RBT, 2), RNT, SM_TOT>>>(b_ih_f, b_ih_b, b_hh_f, b_hh_b, out);
}